// round 6
// baseline (speedup 1.0000x reference)
#include <cuda_runtime.h>

#define B_SZ   65536
#define IN_SZ  512
#define HID_SZ 512
#define FAN    1024
#define NZ     32          // NGATES * NQ
#define THREADS 512
#define NBLK   (B_SZ / THREADS)   // 128

typedef unsigned long long u64;

// Pre-transposed weights (filled by prep_kernel each launch; deterministic).
__device__ float g_W1t[FAN * NZ];          // [k][gq]     gq = g*8+q
__device__ float g_W2t[4 * 8 * HID_SZ];    // [g][q][h]

__device__ __forceinline__ u64 pk2(float a, float b) {
    u64 r; asm("mov.b64 %0, {%1,%2};" : "=l"(r) : "f"(a), "f"(b)); return r;
}
__device__ __forceinline__ void upk2(u64 v, float& a, float& b) {
    asm("mov.b64 {%0,%1}, %2;" : "=f"(a), "=f"(b) : "l"(v));
}
// packed dual-FMA on Blackwell fp32 pipe: d = a*b + d (two lanes)
__device__ __forceinline__ void ffma2(u64& d, u64 a, u64 b) {
    asm("fma.rn.f32x2 %0, %1, %2, %0;" : "+l"(d) : "l"(a), "l"(b));
}
// accurate tanh (only for the 32 z values per row; error ~1e-7)
__device__ __forceinline__ float tanh_acc(float xv) {
    float s = __fdividef(1.0f, 1.0f + __expf(-2.0f * xv));
    return 2.0f * s - 1.0f;
}
// HW MUFU.TANH (1 MUFU op), rel err ~2^-11 — plenty for sigmoid gates
__device__ __forceinline__ float tanh_fast(float xv) {
    float y; asm("tanh.approx.f32 %0, %1;" : "=f"(y) : "f"(xv)); return y;
}
__device__ __forceinline__ float sigm_fast(float xv) {
    return fmaf(tanh_fast(0.5f * xv), 0.5f, 0.5f);
}

__global__ void prep_kernel(const float* __restrict__ W1, const float* __restrict__ W2) {
    int t = blockIdx.x * blockDim.x + threadIdx.x;
    if (t < FAN * NZ) {
        // W1 is [4][8][1024] -> W1t[k][gq]
        int k = t >> 5, gq = t & 31;
        g_W1t[t] = W1[gq * FAN + k];
    } else {
        int t2 = t - FAN * NZ;
        if (t2 < 4 * 8 * HID_SZ) {
            // W2 is [4][512][8] -> W2t[g][q][h]
            int g = t2 >> 12, rem = t2 & 4095, q = rem >> 9, hh = rem & 511;
            g_W2t[t2] = W2[g * 4096 + hh * 8 + q];
        }
    }
}

// One 512-wide half of the fan-in, one row, distance-2 software pipeline.
__device__ __forceinline__ void gemm1_half(const float* __restrict__ p,
                                           const float* __restrict__ Wbase,
                                           u64* acc) {
    // blocks of 8 k; keep 2 blocks (32 floats, 8 LDG.128) in flight
    float4 a0 = *(const float4*)(p);
    float4 a1 = *(const float4*)(p + 4);
    float4 b0 = *(const float4*)(p + 8);
    float4 b1 = *(const float4*)(p + 12);
    #pragma unroll 1
    for (int k0 = 0; k0 < 512; k0 += 8) {
        float4 c0 = a0, c1 = a1;
        a0 = b0; a1 = b1;
        int kn = k0 + 16;
        if (kn >= 512) kn = k0;                // clamped (reload, harmless)
        b0 = *(const float4*)(p + kn);
        b1 = *(const float4*)(p + kn + 4);

        float cv[8] = {c0.x, c0.y, c0.z, c0.w, c1.x, c1.y, c1.z, c1.w};
        #pragma unroll
        for (int kk = 0; kk < 8; kk++) {
            u64 a2 = pk2(cv[kk], cv[kk]);
            const ulonglong2* wr = (const ulonglong2*)(Wbase + (k0 + kk) * NZ);
            #pragma unroll
            for (int pp = 0; pp < 8; pp++) {
                ulonglong2 w = wr[pp];         // LDS.128 uniform broadcast
                ffma2(acc[2*pp],     a2, w.x);
                ffma2(acc[2*pp + 1], a2, w.y);
            }
        }
    }
}

__global__ __launch_bounds__(THREADS, 1)
void lstm_kernel(const float* __restrict__ x, const float* __restrict__ h,
                 const float* __restrict__ c, const float* __restrict__ b1,
                 const float* __restrict__ b2, float* __restrict__ out) {
    extern __shared__ float smem[];
    float* W1s = smem;               // 32768 floats (128 KB)  [k][32]
    float* W2s = smem + 32768;       // 16384 floats ( 64 KB)  [g][q][512]
    float* b2s = smem + 49152;       //  2048 floats (  8 KB)  [g][512]
    float* b1s = smem + 51200;       //    32 floats

    const int tid = threadIdx.x;
    {   // cooperative smem fill (coalesced, conflict-free)
        float4* d1 = (float4*)W1s; const float4* s1 = (const float4*)g_W1t;
        #pragma unroll
        for (int i = 0; i < 16; i++) d1[tid + i * THREADS] = s1[tid + i * THREADS];
        float4* d2 = (float4*)W2s; const float4* s2 = (const float4*)g_W2t;
        #pragma unroll
        for (int i = 0; i < 8; i++) d2[tid + i * THREADS] = s2[tid + i * THREADS];
        float4* d3 = (float4*)b2s; const float4* s3 = (const float4*)b2;
        d3[tid] = s3[tid];
        if (tid < 32) b1s[tid] = b1[tid];
    }
    __syncthreads();

    const int row = blockIdx.x * THREADS + tid;
    const float* xr = x + (size_t)row * IN_SZ;
    const float* hr = h + (size_t)row * HID_SZ;

    // ---------------- GEMM1: z_pre[32] = combined[1024] . W1t ----------------
    u64 acc[16];
    #pragma unroll
    for (int p = 0; p < 16; p++) acc[p] = 0ULL;

    gemm1_half(xr, W1s,            acc);   // k in [0,512): x
    gemm1_half(hr, W1s + 512 * NZ, acc);   // k in [512,1024): h

    // z = tanh(z_pre + b1); dup-pack each z into both f32x2 lanes
    u64 z2[32];
    #pragma unroll
    for (int p = 0; p < 16; p++) {
        float a, b; upk2(acc[p], a, b);
        a = tanh_acc(a + b1s[2*p]);
        b = tanh_acc(b + b1s[2*p + 1]);
        z2[2*p]     = pk2(a, a);
        z2[2*p + 1] = pk2(b, b);
    }

    // ---------------- GEMM2 + gating epilogue (c prefetched 2 iters ahead) ----------------
    const float* cr  = c   + (size_t)row * HID_SZ;
    float* hnr = out + (size_t)row * HID_SZ;
    float* cnr = out + (size_t)B_SZ * HID_SZ + (size_t)row * HID_SZ;

    float4 cvA = *(const float4*)(cr);
    float4 cvB = *(const float4*)(cr + 4);

    #pragma unroll 1
    for (int h0 = 0; h0 < HID_SZ; h0 += 4) {
        float4 cv = cvA;
        cvA = cvB;
        int hn2 = h0 + 8;
        if (hn2 >= HID_SZ) hn2 = h0;           // clamp
        cvB = *(const float4*)(cr + hn2);

        float pre[4][4];
        #pragma unroll
        for (int g = 0; g < 4; g++) {
            ulonglong2 bb = *(const ulonglong2*)(b2s + g * HID_SZ + h0);
            u64 a0 = bb.x, a1 = bb.y;          // pairs (h0,h0+1) and (h0+2,h0+3)
            const float* wg = W2s + g * (8 * HID_SZ) + h0;
            #pragma unroll
            for (int q = 0; q < 8; q++) {
                ulonglong2 w = *(const ulonglong2*)(wg + q * HID_SZ);
                ffma2(a0, z2[g*8 + q], w.x);
                ffma2(a1, z2[g*8 + q], w.y);
            }
            upk2(a0, pre[g][0], pre[g][1]);
            upk2(a1, pre[g][2], pre[g][3]);
        }
        float ca[4] = {cv.x, cv.y, cv.z, cv.w};
        float hn[4], cn[4];
        #pragma unroll
        for (int j = 0; j < 4; j++) {
            float ig = sigm_fast(pre[0][j]);
            float fg = sigm_fast(pre[1][j]);
            float og = sigm_fast(pre[2][j]);
            float gg = sigm_fast(pre[3][j]);
            float cj = fmaf(fg, ca[j], ig * gg);
            cn[j] = cj;
            hn[j] = og * tanh_fast(cj);
        }
        *(float4*)(hnr + h0) = make_float4(hn[0], hn[1], hn[2], hn[3]);
        *(float4*)(cnr + h0) = make_float4(cn[0], cn[1], cn[2], cn[3]);
    }
}

extern "C" void kernel_launch(void* const* d_in, const int* in_sizes, int n_in,
                              void* d_out, int out_size) {
    const float* x  = (const float*)d_in[0];
    const float* h  = (const float*)d_in[1];
    const float* c  = (const float*)d_in[2];
    const float* W1 = (const float*)d_in[3];
    const float* b1 = (const float*)d_in[4];
    const float* W2 = (const float*)d_in[5];
    const float* b2 = (const float*)d_in[6];
    float* out = (float*)d_out;

    prep_kernel<<<192, 256>>>(W1, W2);   // 192*256 = 49152 = 32768 + 16384

    const size_t smem_bytes = (size_t)(32768 + 16384 + 2048 + 32) * sizeof(float); // 204,928 B
    cudaFuncSetAttribute(lstm_kernel, cudaFuncAttributeMaxDynamicSharedMemorySize,
                         (int)smem_bytes);
    lstm_kernel<<<NBLK, THREADS, smem_bytes>>>(x, h, c, b1, b2, out);
}

// round 8
// speedup vs baseline: 1.7606x; 1.7606x over previous
#include <cuda_runtime.h>
#include <cuda_bf16.h>
#include <cstdint>

#define B_SZ    65536
#define HID_SZ  512
#define THREADS 256
#define NBLK    512        // 512 CTAs x 128 rows
#define MTILE   128
#define NCHUNK  16         // K = 1024 in chunks of 64
#define AROW    144        // bytes per smem row: 64 bf16 = 128B + 16B pad (ldmatrix conflict-free)

typedef unsigned long long u64;

// ---------------- smem layout (bytes) ----------------
// phase1: A_hi [128][144]=18432 @0, A_lo @18432, W1c hi @36864 (32*144=4608), lo @41472 (end 46080)
// phase2: W2s [32][512]f32 = 65536 @0 (overlays staging)
// b2s @65536 (8192, loaded at start, untouched by phase1)   Z2 @73728 (128*33 u64 = 33792)
// b1s @107520 (128)
#define OFF_A_HI   0
#define OFF_A_LO   18432
#define OFF_W_HI   36864
#define OFF_W_LO   41472
#define OFF_W2S    0
#define OFF_B2S    65536
#define OFF_Z2     73728
#define OFF_B1     107520
#define SMEM_TOTAL 107648

// ---------------- device globals (prep output) ----------------
// W1 per chunk: [chunk][2(hi,lo)][32 gq][144B]  (row = gq, 64 bf16 k-contig + pad)
__device__ __align__(16) unsigned char g_W1c[NCHUNK * 9216];
__device__ float g_W2t[4 * 8 * HID_SZ];        // [g][q][h]

// ---------------- helpers ----------------
__device__ __forceinline__ uint32_t smem_u32(const void* p) {
    uint32_t a;
    asm("{ .reg .u64 t; cvta.to.shared.u64 t, %1; cvt.u32.u64 %0, t; }" : "=r"(a) : "l"(p));
    return a;
}
__device__ __forceinline__ u64 pk2(float a, float b) {
    u64 r; asm("mov.b64 %0, {%1,%2};" : "=l"(r) : "f"(a), "f"(b)); return r;
}
__device__ __forceinline__ void upk2(u64 v, float& a, float& b) {
    asm("mov.b64 {%0,%1}, %2;" : "=f"(a), "=f"(b) : "l"(v));
}
__device__ __forceinline__ void ffma2(u64& d, u64 a, u64 b) {
    asm("fma.rn.f32x2 %0, %1, %2, %0;" : "+l"(d) : "l"(a), "l"(b));
}
// bf16x2 pack: low half = f0, high half = f1
__device__ __forceinline__ uint32_t cvt2bf(float f0, float f1) {
    uint32_t r; asm("cvt.rn.bf16x2.f32 %0, %1, %2;" : "=r"(r) : "f"(f1), "f"(f0)); return r;
}
__device__ __forceinline__ float tanh_acc(float xv) {
    float s = __fdividef(1.0f, 1.0f + __expf(-2.0f * xv));
    return 2.0f * s - 1.0f;
}
__device__ __forceinline__ float tanh_fast(float xv) {
    float y; asm("tanh.approx.f32 %0, %1;" : "=f"(y) : "f"(xv)); return y;
}
__device__ __forceinline__ float sigm_fast(float xv) {
    return fmaf(tanh_fast(0.5f * xv), 0.5f, 0.5f);
}
#define LDSM4(f, addr)                                                          \
    asm volatile("ldmatrix.sync.aligned.m8n8.x4.shared.b16 {%0,%1,%2,%3}, [%4];" \
        : "=r"((f)[0]), "=r"((f)[1]), "=r"((f)[2]), "=r"((f)[3]) : "r"(addr))

__device__ __forceinline__ void mma16816(float* d, const uint32_t* a,
                                         uint32_t b0, uint32_t b1) {
    asm volatile(
        "mma.sync.aligned.m16n8k16.row.col.f32.bf16.bf16.f32 "
        "{%0,%1,%2,%3}, {%4,%5,%6,%7}, {%8,%9}, {%0,%1,%2,%3};"
        : "+f"(d[0]), "+f"(d[1]), "+f"(d[2]), "+f"(d[3])
        : "r"(a[0]), "r"(a[1]), "r"(a[2]), "r"(a[3]), "r"(b0), "r"(b1));
}

// ---------------- prep: split W1 to bf16 hi/lo padded chunks; transpose W2 ----------------
__global__ void prep_kernel(const float* __restrict__ W1, const float* __restrict__ W2) {
    int t = blockIdx.x * blockDim.x + threadIdx.x;
    if (t < NCHUNK * 32 * 64) {
        int ck = t >> 11, n = (t >> 6) & 31, kl = t & 63;
        float w = W1[n * 1024 + ck * 64 + kl];        // W1[gq][k]
        __nv_bfloat16 hb = __float2bfloat16_rn(w);
        float hf = __bfloat162float(hb);
        __nv_bfloat16 lb = __float2bfloat16_rn(w - hf);
        uint32_t base = ck * 9216 + n * AROW + kl * 2;
        *(__nv_bfloat16*)(g_W1c + base)        = hb;
        *(__nv_bfloat16*)(g_W1c + base + 4608) = lb;
    } else {
        int t2 = t - NCHUNK * 32 * 64;
        if (t2 < 4 * 8 * HID_SZ) {
            int g = t2 >> 12, rem = t2 & 4095, q = rem >> 9, hh = rem & 511;
            g_W2t[t2] = W2[g * 4096 + hh * 8 + q];
        }
    }
}

// ---------------- main fused kernel ----------------
__global__ __launch_bounds__(THREADS, 2)
void lstm_kernel(const float* __restrict__ x, const float* __restrict__ h,
                 const float* __restrict__ c, const float* __restrict__ b1,
                 const float* __restrict__ b2, float* __restrict__ out) {
    extern __shared__ __align__(16) char smem[];
    const uint32_t sb = smem_u32(smem);
    const int tid = threadIdx.x;
    const int wid = tid >> 5, lid = tid & 31;
    const size_t row0 = (size_t)blockIdx.x * MTILE;

    // b2s + b1s live in regions phase1 never touches — load once up front
    ((uint4*)(smem + OFF_B2S))[tid]       = ((const uint4*)b2)[tid];
    ((uint4*)(smem + OFF_B2S))[tid + 256] = ((const uint4*)b2)[tid + 256];
    if (tid < 32) ((float*)(smem + OFF_B1))[tid] = b1[tid];

    // ================= phase 1: GEMM1 via mma.sync bf16 (hi/lo split) =================
    float d[4][4];           // d[ntile][reg] — warp computes rows wid*16..+15, all 32 cols
    #pragma unroll
    for (int nt = 0; nt < 4; nt++)
        #pragma unroll
        for (int j = 0; j < 4; j++) d[nt][j] = 0.0f;

    float4 v[8];             // A chunk prefetch: 128 rows x 64 k
    uint4  wv[3];            // W1 chunk prefetch: 9216B = 576 uint4

    // preload chunk 0
    {
        const float* src = x + row0 * 512;
        #pragma unroll
        for (int j = 0; j < 8; j++) {
            int i = tid + j * THREADS, r = i >> 4, k4 = i & 15;
            v[j] = *(const float4*)(src + (size_t)r * 512 + k4 * 4);
        }
        #pragma unroll
        for (int j = 0; j < 3; j++) {
            int i = tid + j * THREADS;
            if (i < 576) wv[j] = ((const uint4*)g_W1c)[i];
        }
    }

    // per-lane ldmatrix address components (constant across chunks)
    const int a_r  = wid * 16 + (lid & 15);
    const int a_kb = (lid >> 4) * 16;                 // byte offset of k-half
    const int b_g  = lid >> 3;
    const int b_n  = (b_g >> 1) * 8 + (lid & 7);
    const int b_kb = (b_g & 1) * 16;
    const uint32_t a_base = sb + OFF_A_HI + a_r * AROW + a_kb;
    const uint32_t b_base = sb + OFF_W_HI + b_n * AROW + b_kb;

    #pragma unroll 1
    for (int ck = 0; ck < NCHUNK; ck++) {
        // ---- store staged chunk to smem (bf16 hi/lo) ----
        #pragma unroll
        for (int j = 0; j < 8; j++) {
            int i = tid + j * THREADS, r = i >> 4, k4 = i & 15;
            uint32_t h01 = cvt2bf(v[j].x, v[j].y);
            uint32_t h23 = cvt2bf(v[j].z, v[j].w);
            float l0 = v[j].x - __uint_as_float(h01 << 16);
            float l1 = v[j].y - __uint_as_float(h01 & 0xFFFF0000u);
            float l2 = v[j].z - __uint_as_float(h23 << 16);
            float l3 = v[j].w - __uint_as_float(h23 & 0xFFFF0000u);
            uint32_t q01 = cvt2bf(l0, l1);
            uint32_t q23 = cvt2bf(l2, l3);
            uint32_t off = (uint32_t)(r * AROW + k4 * 8);
            u64 hi; asm("mov.b64 %0, {%1,%2};" : "=l"(hi) : "r"(h01), "r"(h23));
            u64 lo; asm("mov.b64 %0, {%1,%2};" : "=l"(lo) : "r"(q01), "r"(q23));
            asm volatile("st.shared.b64 [%0], %1;" :: "r"(sb + OFF_A_HI + off), "l"(hi) : "memory");
            asm volatile("st.shared.b64 [%0], %1;" :: "r"(sb + OFF_A_LO + off), "l"(lo) : "memory");
        }
        #pragma unroll
        for (int j = 0; j < 3; j++) {
            int i = tid + j * THREADS;
            if (i < 576) ((uint4*)(smem + OFF_W_HI))[i] = wv[j];
        }
        __syncthreads();

        // ---- prefetch next chunk (overlaps with MMA below) ----
        if (ck + 1 < NCHUNK) {
            int cn = ck + 1;
            const float* src = ((cn < 8) ? x : h) + row0 * 512 + (size_t)(cn & 7) * 64;
            #pragma unroll
            for (int j = 0; j < 8; j++) {
                int i = tid + j * THREADS, r = i >> 4, k4 = i & 15;
                v[j] = *(const float4*)(src + (size_t)r * 512 + k4 * 4);
            }
            #pragma unroll
            for (int j = 0; j < 3; j++) {
                int i = tid + j * THREADS;
                if (i < 576) wv[j] = ((const uint4*)(g_W1c + (size_t)cn * 9216))[i];
            }
        }

        // ---- consume: 4 k16-steps of mma ----
        #pragma unroll
        for (int ks = 0; ks < 4; ks++) {
            uint32_t ah[4], al[4], bh0[4], bh1[4], bl0[4], bl1[4];
            uint32_t aa = a_base + ks * 32;
            LDSM4(ah, aa);
            LDSM4(al, aa + (OFF_A_LO - OFF_A_HI));
            uint32_t ba = b_base + ks * 32;
            LDSM4(bh0, ba);                 // n 0-15  hi
            LDSM4(bh1, ba + 16 * AROW);     // n 16-31 hi
            LDSM4(bl0, ba + 4608);          // n 0-15  lo
            LDSM4(bl1, ba + 4608 + 16 * AROW);
            mma16816(d[0], ah, bh0[0], bh0[1]);
            mma16816(d[1], ah, bh0[2], bh0[3]);
            mma16816(d[2], ah, bh1[0], bh1[1]);
            mma16816(d[3], ah, bh1[2], bh1[3]);
            mma16816(d[0], ah, bl0[0], bl0[1]);
            mma16816(d[1], ah, bl0[2], bl0[3]);
            mma16816(d[2], ah, bl1[0], bl1[1]);
            mma16816(d[3], ah, bl1[2], bl1[3]);
            mma16816(d[0], al, bh0[0], bh0[1]);
            mma16816(d[1], al, bh0[2], bh0[3]);
            mma16816(d[2], al, bh1[0], bh1[1]);
            mma16816(d[3], al, bh1[2], bh1[3]);
        }
        __syncthreads();     // staging consumed; next iter may overwrite
    }

    // ---- z epilogue: bias + tanh, dup-pack into smem Z2[row][33 u64] ----
    {
        const float* b1s = (const float*)(smem + OFF_B1);
        u64* zsm = (u64*)(smem + OFF_Z2);
        int rb = wid * 16 + (lid >> 2);
        int cb = (lid & 3) * 2;
        #pragma unroll
        for (int nt = 0; nt < 4; nt++) {
            int c0 = nt * 8 + cb;
            float bA = b1s[c0], bB = b1s[c0 + 1];
            float z00 = tanh_acc(d[nt][0] + bA);
            float z01 = tanh_acc(d[nt][1] + bB);
            float z10 = tanh_acc(d[nt][2] + bA);
            float z11 = tanh_acc(d[nt][3] + bB);
            zsm[rb * 33 + c0]           = pk2(z00, z00);
            zsm[rb * 33 + c0 + 1]       = pk2(z01, z01);
            zsm[(rb + 8) * 33 + c0]     = pk2(z10, z10);
            zsm[(rb + 8) * 33 + c0 + 1] = pk2(z11, z11);
        }
    }
    __syncthreads();

    // ---- overlay W2t onto dead staging region ----
    {
        uint4* dw = (uint4*)(smem + OFF_W2S);
        const uint4* swv = (const uint4*)g_W2t;
        #pragma unroll
        for (int j = 0; j < 16; j++) dw[tid + j * THREADS] = swv[tid + j * THREADS];
    }
    __syncthreads();

    // ================= phase 2: GEMM2 + gating, warp-per-row, lanes split h =================
    const float* W2s = (const float*)(smem + OFF_W2S);
    const float* b2s = (const float*)(smem + OFF_B2S);

    #pragma unroll 1
    for (int rr = 0; rr < 16; rr++) {
        const int rloc = wid * 16 + rr;
        const size_t row = row0 + rloc;
        const u64* zrow = (const u64*)(smem + OFF_Z2 + rloc * 264);
        const float* crow = c + row * HID_SZ;
        float* hrow = out + row * HID_SZ;
        float* crw  = out + (size_t)B_SZ * HID_SZ + row * HID_SZ;

        #pragma unroll 1
        for (int pass = 0; pass < 4; pass++) {
            const int hh = pass * 128 + lid * 4;
            float4 cv = *(const float4*)(crow + hh);       // coalesced
            float pre[4][4];
            #pragma unroll
            for (int g = 0; g < 4; g++) {
                ulonglong2 bb = *(const ulonglong2*)(b2s + g * 512 + hh);
                u64 a0 = bb.x, a1 = bb.y;
                const float* wg = W2s + (g * 8) * 512 + hh;
                #pragma unroll
                for (int q = 0; q < 8; q++) {
                    ulonglong2 w = *(const ulonglong2*)(wg + q * 512);  // lane-distinct, conflict-free
                    u64 zd = zrow[g * 8 + q];                            // uniform broadcast
                    ffma2(a0, zd, w.x);
                    ffma2(a1, zd, w.y);
                }
                upk2(a0, pre[g][0], pre[g][1]);
                upk2(a1, pre[g][2], pre[g][3]);
            }
            float ca[4] = {cv.x, cv.y, cv.z, cv.w};
            float hn[4], cn[4];
            #pragma unroll
            for (int j = 0; j < 4; j++) {
                float ig = sigm_fast(pre[0][j]);
                float fg = sigm_fast(pre[1][j]);
                float og = sigm_fast(pre[2][j]);
                float gg = sigm_fast(pre[3][j]);
                float cj = fmaf(fg, ca[j], ig * gg);
                cn[j] = cj;
                hn[j] = og * tanh_fast(cj);
            }
            *(float4*)(hrow + hh) = make_float4(hn[0], hn[1], hn[2], hn[3]);   // coalesced
            *(float4*)(crw  + hh) = make_float4(cn[0], cn[1], cn[2], cn[3]);
        }
    }
}

extern "C" void kernel_launch(void* const* d_in, const int* in_sizes, int n_in,
                              void* d_out, int out_size) {
    const float* x  = (const float*)d_in[0];
    const float* h  = (const float*)d_in[1];
    const float* c  = (const float*)d_in[2];
    const float* W1 = (const float*)d_in[3];
    const float* b1 = (const float*)d_in[4];
    const float* W2 = (const float*)d_in[5];
    const float* b2 = (const float*)d_in[6];
    float* out = (float*)d_out;

    prep_kernel<<<192, 256>>>(W1, W2);   // 49152 threads: 32768 W1 + 16384 W2

    cudaFuncSetAttribute(lstm_kernel, cudaFuncAttributeMaxDynamicSharedMemorySize, SMEM_TOTAL);
    lstm_kernel<<<NBLK, THREADS, SMEM_TOTAL>>>(x, h, c, b1, b2, out);
}

// round 9
// speedup vs baseline: 2.1015x; 1.1936x over previous
#include <cuda_runtime.h>
#include <cuda_bf16.h>
#include <cstdint>

#define B_SZ    65536
#define HID_SZ  512
#define THREADS 256
#define NBLK    512        // 512 CTAs x 128 rows
#define MTILE   128
#define NCHUNK  16         // K = 1024 in chunks of 64
#define AROW    144        // bytes per smem row: 64 bf16 = 128B + 16B pad
#define ZSTRIDE 36         // floats per z row (32 + 4 pad, keeps 16B alignment)

typedef unsigned long long u64;

// ---------------- smem layout (bytes) ----------------
// phase1: A_hi [128][144]=18432 @0, A_lo @18432, W1c hi @36864 (4608), lo @41472 (end 46080)
// phase2: W2s [32][512] f32 = 65536 @0 (overlays staging)
// b2s @65536 (8192, loaded at start, untouched by phase1)
// Z   @73728 (128*36*4 = 18432)    b1s @92160 (128)
#define OFF_A_HI   0
#define OFF_A_LO   18432
#define OFF_W_HI   36864
#define OFF_W_LO   41472
#define OFF_W2S    0
#define OFF_B2S    65536
#define OFF_Z      73728
#define OFF_B1     92160
#define SMEM_TOTAL 92288

// ---------------- device globals (prep output) ----------------
__device__ __align__(16) unsigned char g_W1c[NCHUNK * 9216];  // [chunk][hi/lo][32 gq][144B]
__device__ float g_W2t[4 * 8 * HID_SZ];                       // [g][q][h]

// ---------------- helpers ----------------
__device__ __forceinline__ uint32_t smem_u32(const void* p) {
    uint32_t a;
    asm("{ .reg .u64 t; cvta.to.shared.u64 t, %1; cvt.u32.u64 %0, t; }" : "=r"(a) : "l"(p));
    return a;
}
__device__ __forceinline__ u64 pk2(float a, float b) {
    u64 r; asm("mov.b64 %0, {%1,%2};" : "=l"(r) : "f"(a), "f"(b)); return r;
}
__device__ __forceinline__ void upk2(u64 v, float& a, float& b) {
    asm("mov.b64 {%0,%1}, %2;" : "=f"(a), "=f"(b) : "l"(v));
}
__device__ __forceinline__ void ffma2(u64& d, u64 a, u64 b) {
    asm("fma.rn.f32x2 %0, %1, %2, %0;" : "+l"(d) : "l"(a), "l"(b));
}
__device__ __forceinline__ uint32_t cvt2bf(float f0, float f1) {
    uint32_t r; asm("cvt.rn.bf16x2.f32 %0, %1, %2;" : "=r"(r) : "f"(f1), "f"(f0)); return r;
}
__device__ __forceinline__ float tanh_acc(float xv) {
    float s = __fdividef(1.0f, 1.0f + __expf(-2.0f * xv));
    return 2.0f * s - 1.0f;
}
__device__ __forceinline__ float tanh_fast(float xv) {
    float y; asm("tanh.approx.f32 %0, %1;" : "=f"(y) : "f"(xv)); return y;
}
__device__ __forceinline__ float sigm_fast(float xv) {
    return fmaf(tanh_fast(0.5f * xv), 0.5f, 0.5f);
}
#define LDSM4(f, addr)                                                          \
    asm volatile("ldmatrix.sync.aligned.m8n8.x4.shared.b16 {%0,%1,%2,%3}, [%4];" \
        : "=r"((f)[0]), "=r"((f)[1]), "=r"((f)[2]), "=r"((f)[3]) : "r"(addr))

__device__ __forceinline__ void mma16816(float* d, const uint32_t* a,
                                         uint32_t b0, uint32_t b1) {
    asm volatile(
        "mma.sync.aligned.m16n8k16.row.col.f32.bf16.bf16.f32 "
        "{%0,%1,%2,%3}, {%4,%5,%6,%7}, {%8,%9}, {%0,%1,%2,%3};"
        : "+f"(d[0]), "+f"(d[1]), "+f"(d[2]), "+f"(d[3])
        : "r"(a[0]), "r"(a[1]), "r"(a[2]), "r"(a[3]), "r"(b0), "r"(b1));
}

// ---------------- prep: split W1 to bf16 hi/lo padded chunks; transpose W2 ----------------
__global__ void prep_kernel(const float* __restrict__ W1, const float* __restrict__ W2) {
    int t = blockIdx.x * blockDim.x + threadIdx.x;
    if (t < NCHUNK * 32 * 64) {
        int ck = t >> 11, n = (t >> 6) & 31, kl = t & 63;
        float w = W1[n * 1024 + ck * 64 + kl];        // W1[gq][k]
        __nv_bfloat16 hb = __float2bfloat16_rn(w);
        float hf = __bfloat162float(hb);
        __nv_bfloat16 lb = __float2bfloat16_rn(w - hf);
        uint32_t base = ck * 9216 + n * AROW + kl * 2;
        *(__nv_bfloat16*)(g_W1c + base)        = hb;
        *(__nv_bfloat16*)(g_W1c + base + 4608) = lb;
    } else {
        int t2 = t - NCHUNK * 32 * 64;
        if (t2 < 4 * 8 * HID_SZ) {
            int g = t2 >> 12, rem = t2 & 4095, q = rem >> 9, hh = rem & 511;
            g_W2t[t2] = W2[g * 4096 + hh * 8 + q];
        }
    }
}

// Compute pre-activation for one gate g, 4 consecutive rows, 4 h per lane.
// zr: base of z for row block (stride ZSTRIDE floats per row).
__device__ __forceinline__ void gate_pre(const float* __restrict__ W2s,
                                         const float* __restrict__ b2s,
                                         const float* __restrict__ zr,
                                         int g, int hh, float pre[4][4]) {
    u64 a[4][2];
    ulonglong2 bb = *(const ulonglong2*)(b2s + g * 512 + hh);
    #pragma unroll
    for (int i = 0; i < 4; i++) { a[i][0] = bb.x; a[i][1] = bb.y; }
    const float* wg = W2s + (g * 8) * 512 + hh;
    #pragma unroll
    for (int half = 0; half < 2; half++) {
        float zz[4][4];
        #pragma unroll
        for (int i = 0; i < 4; i++) {
            float4 z4 = *(const float4*)(zr + i * ZSTRIDE + g * 8 + half * 4);  // broadcast
            zz[i][0] = z4.x; zz[i][1] = z4.y; zz[i][2] = z4.z; zz[i][3] = z4.w;
        }
        #pragma unroll
        for (int q = 0; q < 4; q++) {
            ulonglong2 w = *(const ulonglong2*)(wg + (half * 4 + q) * 512);  // lane-distinct
            #pragma unroll
            for (int i = 0; i < 4; i++) {
                u64 zd = pk2(zz[i][q], zz[i][q]);
                ffma2(a[i][0], zd, w.x);
                ffma2(a[i][1], zd, w.y);
            }
        }
    }
    #pragma unroll
    for (int i = 0; i < 4; i++) {
        upk2(a[i][0], pre[i][0], pre[i][1]);
        upk2(a[i][1], pre[i][2], pre[i][3]);
    }
}

// ---------------- main fused kernel ----------------
__global__ __launch_bounds__(THREADS, 2)
void lstm_kernel(const float* __restrict__ x, const float* __restrict__ h,
                 const float* __restrict__ c, const float* __restrict__ b1,
                 const float* __restrict__ b2, float* __restrict__ out) {
    extern __shared__ __align__(16) char smem[];
    const uint32_t sb = smem_u32(smem);
    const int tid = threadIdx.x;
    const int wid = tid >> 5, lid = tid & 31;
    const size_t row0 = (size_t)blockIdx.x * MTILE;

    // b2s + b1s live in regions phase1 never touches — load once up front
    ((uint4*)(smem + OFF_B2S))[tid]       = ((const uint4*)b2)[tid];
    ((uint4*)(smem + OFF_B2S))[tid + 256] = ((const uint4*)b2)[tid + 256];
    if (tid < 32) ((float*)(smem + OFF_B1))[tid] = b1[tid];

    // ================= phase 1: GEMM1 via mma.sync bf16 (hi/lo split) =================
    float d[4][4];
    #pragma unroll
    for (int nt = 0; nt < 4; nt++)
        #pragma unroll
        for (int j = 0; j < 4; j++) d[nt][j] = 0.0f;

    float4 v[8];
    uint4  wv[3];

    {   // preload chunk 0
        const float* src = x + row0 * 512;
        #pragma unroll
        for (int j = 0; j < 8; j++) {
            int i = tid + j * THREADS, r = i >> 4, k4 = i & 15;
            v[j] = *(const float4*)(src + (size_t)r * 512 + k4 * 4);
        }
        #pragma unroll
        for (int j = 0; j < 3; j++) {
            int i = tid + j * THREADS;
            if (i < 576) wv[j] = ((const uint4*)g_W1c)[i];
        }
    }

    const int a_r  = wid * 16 + (lid & 15);
    const int a_kb = (lid >> 4) * 16;
    const int b_g  = lid >> 3;
    const int b_n  = (b_g >> 1) * 8 + (lid & 7);
    const int b_kb = (b_g & 1) * 16;
    const uint32_t a_base = sb + OFF_A_HI + a_r * AROW + a_kb;
    const uint32_t b_base = sb + OFF_W_HI + b_n * AROW + b_kb;

    #pragma unroll 1
    for (int ck = 0; ck < NCHUNK; ck++) {
        #pragma unroll
        for (int j = 0; j < 8; j++) {
            int i = tid + j * THREADS, r = i >> 4, k4 = i & 15;
            uint32_t h01 = cvt2bf(v[j].x, v[j].y);
            uint32_t h23 = cvt2bf(v[j].z, v[j].w);
            float l0 = v[j].x - __uint_as_float(h01 << 16);
            float l1 = v[j].y - __uint_as_float(h01 & 0xFFFF0000u);
            float l2 = v[j].z - __uint_as_float(h23 << 16);
            float l3 = v[j].w - __uint_as_float(h23 & 0xFFFF0000u);
            uint32_t q01 = cvt2bf(l0, l1);
            uint32_t q23 = cvt2bf(l2, l3);
            uint32_t off = (uint32_t)(r * AROW + k4 * 8);
            u64 hi; asm("mov.b64 %0, {%1,%2};" : "=l"(hi) : "r"(h01), "r"(h23));
            u64 lo; asm("mov.b64 %0, {%1,%2};" : "=l"(lo) : "r"(q01), "r"(q23));
            asm volatile("st.shared.b64 [%0], %1;" :: "r"(sb + OFF_A_HI + off), "l"(hi) : "memory");
            asm volatile("st.shared.b64 [%0], %1;" :: "r"(sb + OFF_A_LO + off), "l"(lo) : "memory");
        }
        #pragma unroll
        for (int j = 0; j < 3; j++) {
            int i = tid + j * THREADS;
            if (i < 576) ((uint4*)(smem + OFF_W_HI))[i] = wv[j];
        }
        __syncthreads();

        if (ck + 1 < NCHUNK) {
            int cn = ck + 1;
            const float* src = ((cn < 8) ? x : h) + row0 * 512 + (size_t)(cn & 7) * 64;
            #pragma unroll
            for (int j = 0; j < 8; j++) {
                int i = tid + j * THREADS, r = i >> 4, k4 = i & 15;
                v[j] = *(const float4*)(src + (size_t)r * 512 + k4 * 4);
            }
            #pragma unroll
            for (int j = 0; j < 3; j++) {
                int i = tid + j * THREADS;
                if (i < 576) wv[j] = ((const uint4*)(g_W1c + (size_t)cn * 9216))[i];
            }
        }

        #pragma unroll
        for (int ks = 0; ks < 4; ks++) {
            uint32_t ah[4], al[4], bh0[4], bh1[4], bl0[4], bl1[4];
            uint32_t aa = a_base + ks * 32;
            LDSM4(ah, aa);
            LDSM4(al, aa + (OFF_A_LO - OFF_A_HI));
            uint32_t ba = b_base + ks * 32;
            LDSM4(bh0, ba);
            LDSM4(bh1, ba + 16 * AROW);
            LDSM4(bl0, ba + 4608);
            LDSM4(bl1, ba + 4608 + 16 * AROW);
            mma16816(d[0], ah, bh0[0], bh0[1]);
            mma16816(d[1], ah, bh0[2], bh0[3]);
            mma16816(d[2], ah, bh1[0], bh1[1]);
            mma16816(d[3], ah, bh1[2], bh1[3]);
            mma16816(d[0], ah, bl0[0], bl0[1]);
            mma16816(d[1], ah, bl0[2], bl0[3]);
            mma16816(d[2], ah, bl1[0], bl1[1]);
            mma16816(d[3], ah, bl1[2], bl1[3]);
            mma16816(d[0], al, bh0[0], bh0[1]);
            mma16816(d[1], al, bh0[2], bh0[3]);
            mma16816(d[2], al, bh1[0], bh1[1]);
            mma16816(d[3], al, bh1[2], bh1[3]);
        }
        __syncthreads();
    }

    // ---- z epilogue: bias + tanh -> plain floats in smem Z[row][ZSTRIDE] ----
    {
        const float* b1s = (const float*)(smem + OFF_B1);
        float* zsm = (float*)(smem + OFF_Z);
        int rb = wid * 16 + (lid >> 2);
        int cb = (lid & 3) * 2;
        #pragma unroll
        for (int nt = 0; nt < 4; nt++) {
            int c0 = nt * 8 + cb;
            float bA = b1s[c0], bB = b1s[c0 + 1];
            float2 zlo = make_float2(tanh_acc(d[nt][0] + bA), tanh_acc(d[nt][1] + bB));
            float2 zhi = make_float2(tanh_acc(d[nt][2] + bA), tanh_acc(d[nt][3] + bB));
            *(float2*)(zsm + rb * ZSTRIDE + c0)       = zlo;
            *(float2*)(zsm + (rb + 8) * ZSTRIDE + c0) = zhi;
        }
    }
    __syncthreads();

    // ---- overlay W2t onto dead staging region ----
    {
        uint4* dw = (uint4*)(smem + OFF_W2S);
        const uint4* swv = (const uint4*)g_W2t;
        #pragma unroll
        for (int j = 0; j < 16; j++) dw[tid + j * THREADS] = swv[tid + j * THREADS];
    }
    __syncthreads();

    // ================= phase 2: GEMM2 + gating, 4 rows per W2 pass =================
    const float* W2s = (const float*)(smem + OFF_W2S);
    const float* b2s = (const float*)(smem + OFF_B2S);
    const float* zf  = (const float*)(smem + OFF_Z);

    #pragma unroll 1
    for (int rb = 0; rb < 4; rb++) {
        const int r0 = wid * 16 + rb * 4;
        const size_t grow = row0 + r0;
        const float* zr = zf + r0 * ZSTRIDE;

        #pragma unroll 1
        for (int pass = 0; pass < 4; pass++) {
            const int hh = pass * 128 + lid * 4;

            // c loads early (cover DRAM latency under the gate math)
            float4 cv[4];
            #pragma unroll
            for (int i = 0; i < 4; i++)
                cv[i] = *(const float4*)(c + (grow + i) * (size_t)HID_SZ + hh);

            float preA[4][4], preB[4][4];
            gate_pre(W2s, b2s, zr, 0, hh, preA);   // i
            gate_pre(W2s, b2s, zr, 3, hh, preB);   // g
            float ig[4][4];
            #pragma unroll
            for (int i = 0; i < 4; i++)
                #pragma unroll
                for (int j = 0; j < 4; j++)
                    ig[i][j] = sigm_fast(preA[i][j]) * sigm_fast(preB[i][j]);
            gate_pre(W2s, b2s, zr, 1, hh, preA);   // f
            gate_pre(W2s, b2s, zr, 2, hh, preB);   // o

            #pragma unroll
            for (int i = 0; i < 4; i++) {
                float ca[4] = {cv[i].x, cv[i].y, cv[i].z, cv[i].w};
                float hn[4], cn[4];
                #pragma unroll
                for (int j = 0; j < 4; j++) {
                    float fg = sigm_fast(preA[i][j]);
                    float og = sigm_fast(preB[i][j]);
                    float cj = fmaf(fg, ca[j], ig[i][j]);
                    cn[j] = cj;
                    hn[j] = og * tanh_fast(cj);
                }
                float* hrow = out + (grow + i) * (size_t)HID_SZ;
                float* crw  = out + (size_t)B_SZ * HID_SZ + (grow + i) * (size_t)HID_SZ;
                *(float4*)(hrow + hh) = make_float4(hn[0], hn[1], hn[2], hn[3]);
                *(float4*)(crw  + hh) = make_float4(cn[0], cn[1], cn[2], cn[3]);
            }
        }
    }
}

extern "C" void kernel_launch(void* const* d_in, const int* in_sizes, int n_in,
                              void* d_out, int out_size) {
    const float* x  = (const float*)d_in[0];
    const float* h  = (const float*)d_in[1];
    const float* c  = (const float*)d_in[2];
    const float* W1 = (const float*)d_in[3];
    const float* b1 = (const float*)d_in[4];
    const float* W2 = (const float*)d_in[5];
    const float* b2 = (const float*)d_in[6];
    float* out = (float*)d_out;

    prep_kernel<<<192, 256>>>(W1, W2);   // 49152 threads: 32768 W1 + 16384 W2

    cudaFuncSetAttribute(lstm_kernel, cudaFuncAttributeMaxDynamicSharedMemorySize, SMEM_TOTAL);
    lstm_kernel<<<NBLK, THREADS, SMEM_TOTAL>>>(x, h, c, b1, b2, out);
}

// round 10
// speedup vs baseline: 2.2074x; 1.0504x over previous
#include <cuda_runtime.h>
#include <cuda_fp16.h>
#include <cstdint>

#define B_SZ    65536
#define HID_SZ  512
#define THREADS 256
#define NBLK    512        // 512 CTAs x 128 rows
#define MTILE   128
#define NCHUNK  16         // K = 1024 in chunks of 64
#define ASTRIDE 68         // f32 per A row (64 + 4 pad -> conflict-free frag LDS)
#define ZSTRIDE 36         // f32 per z row

typedef unsigned long long u64;

// ---------------- smem layout (bytes) ----------------
// phase1: A0 @0 (128*272=34816), A1 @34816 (->69632),
//         W0 @69632 (32*272=8704), W1b @78336 (->87040)
// b2s @87040 (8192), b1 @95232 (128)      total 95360
// phase2 overlay: W2h fp16 [32][512] @0 (32768), Z @32768 (128*36*4=18432 ->51200)
#define OFF_A0    0
#define OFF_A1    34816
#define OFF_W0    69632
#define OFF_W1B   78336
#define OFF_B2S   87040
#define OFF_B1    95232
#define OFF_W2H   0
#define OFF_Z     32768
#define SMEM_TOTAL 95360

// ---------------- device globals (prep output) ----------------
__device__ __align__(16) float  g_W1r[32 * 1024];   // W1 rounded-to-tf32, [gq][k]
__device__ __align__(16) __half g_W2h[32 * 512];    // W2 transposed fp16, [gq][h]

// ---------------- helpers ----------------
__device__ __forceinline__ uint32_t smem_u32(const void* p) {
    uint32_t a;
    asm("{ .reg .u64 t; cvta.to.shared.u64 t, %1; cvt.u32.u64 %0, t; }" : "=r"(a) : "l"(p));
    return a;
}
__device__ __forceinline__ u64 pk2(float a, float b) {
    u64 r; asm("mov.b64 %0, {%1,%2};" : "=l"(r) : "f"(a), "f"(b)); return r;
}
__device__ __forceinline__ void upk2(u64 v, float& a, float& b) {
    asm("mov.b64 {%0,%1}, %2;" : "=f"(a), "=f"(b) : "l"(v));
}
__device__ __forceinline__ void ffma2(u64& d, u64 a, u64 b) {
    asm("fma.rn.f32x2 %0, %1, %2, %0;" : "+l"(d) : "l"(a), "l"(b));
}
__device__ __forceinline__ float tanh_acc(float xv) {
    float s = __fdividef(1.0f, 1.0f + __expf(-2.0f * xv));
    return 2.0f * s - 1.0f;
}
__device__ __forceinline__ float tanh_fast(float xv) {
    float y; asm("tanh.approx.f32 %0, %1;" : "=f"(y) : "f"(xv)); return y;
}
__device__ __forceinline__ float sigm_fast(float xv) {
    return fmaf(tanh_fast(0.5f * xv), 0.5f, 0.5f);
}
__device__ __forceinline__ uint32_t lds32(uint32_t a) {
    uint32_t v; asm volatile("ld.shared.b32 %0, [%1];" : "=r"(v) : "r"(a)); return v;
}
#define CP16(dst, src) \
    asm volatile("cp.async.ca.shared.global [%0], [%1], 16;" :: "r"(dst), "l"(src))
#define CP_COMMIT()  asm volatile("cp.async.commit_group;" ::: "memory")
#define CP_WAIT1()   asm volatile("cp.async.wait_group 1;" ::: "memory")
#define CP_WAIT0()   asm volatile("cp.async.wait_group 0;" ::: "memory")

__device__ __forceinline__ void mma_tf32(float* d, uint32_t a0, uint32_t a1,
                                         uint32_t a2, uint32_t a3,
                                         uint32_t b0, uint32_t b1) {
    asm volatile(
        "mma.sync.aligned.m16n8k8.row.col.f32.tf32.tf32.f32 "
        "{%0,%1,%2,%3}, {%4,%5,%6,%7}, {%8,%9}, {%0,%1,%2,%3};"
        : "+f"(d[0]), "+f"(d[1]), "+f"(d[2]), "+f"(d[3])
        : "r"(a0), "r"(a1), "r"(a2), "r"(a3), "r"(b0), "r"(b1));
}

// ---------------- prep: round W1 to tf32; transpose W2 -> fp16 ----------------
__global__ void prep_kernel(const float* __restrict__ W1, const float* __restrict__ W2) {
    int t = blockIdx.x * blockDim.x + threadIdx.x;
    if (t < 32 * 1024) {
        float w = W1[t];                                   // [gq][k] flat
        float r; asm("cvt.rna.tf32.f32 %0, %1;" : "=f"(r) : "f"(w));
        g_W1r[t] = r;
    } else {
        int t2 = t - 32 * 1024;
        if (t2 < 32 * 512) {
            int g = t2 >> 12, rem = t2 & 4095, q = rem >> 9, hh = rem & 511;
            g_W2h[t2] = __float2half(W2[g * 4096 + hh * 8 + q]);  // W2[g][h][q]
        }
    }
}

// gate pre-activation: one gate, 4 rows, 4 h per lane; W2 in fp16 smem
__device__ __forceinline__ void gate_pre(const __half* __restrict__ W2h,
                                         const float* __restrict__ b2s,
                                         const float* __restrict__ zr,
                                         int g, int hh, float pre[4][4]) {
    u64 a[4][2];
    ulonglong2 bb = *(const ulonglong2*)(b2s + g * 512 + hh);
    #pragma unroll
    for (int i = 0; i < 4; i++) { a[i][0] = bb.x; a[i][1] = bb.y; }
    const __half* wg = W2h + (g * 8) * 512 + hh;
    #pragma unroll
    for (int half_ = 0; half_ < 2; half_++) {
        float zz[4][4];
        #pragma unroll
        for (int i = 0; i < 4; i++) {
            float4 z4 = *(const float4*)(zr + i * ZSTRIDE + g * 8 + half_ * 4);  // broadcast
            zz[i][0] = z4.x; zz[i][1] = z4.y; zz[i][2] = z4.z; zz[i][3] = z4.w;
        }
        #pragma unroll
        for (int q = 0; q < 4; q++) {
            uint2 wl = *(const uint2*)(wg + (half_ * 4 + q) * 512);   // 4 fp16, 2 wf
            __half2 p0 = *reinterpret_cast<__half2*>(&wl.x);
            __half2 p1 = *reinterpret_cast<__half2*>(&wl.y);
            float2 f0 = __half22float2(p0);
            float2 f1 = __half22float2(p1);
            u64 wx = pk2(f0.x, f0.y);
            u64 wy = pk2(f1.x, f1.y);
            #pragma unroll
            for (int i = 0; i < 4; i++) {
                u64 zd = pk2(zz[i][q], zz[i][q]);
                ffma2(a[i][0], zd, wx);
                ffma2(a[i][1], zd, wy);
            }
        }
    }
    #pragma unroll
    for (int i = 0; i < 4; i++) {
        upk2(a[i][0], pre[i][0], pre[i][1]);
        upk2(a[i][1], pre[i][2], pre[i][3]);
    }
}

// ---------------- main fused kernel ----------------
__global__ __launch_bounds__(THREADS, 2)
void lstm_kernel(const float* __restrict__ x, const float* __restrict__ h,
                 const float* __restrict__ c, const float* __restrict__ b1,
                 const float* __restrict__ b2, float* __restrict__ out) {
    extern __shared__ __align__(16) char smem[];
    const uint32_t sb = smem_u32(smem);
    const int tid = threadIdx.x;
    const int wid = tid >> 5, lid = tid & 31;
    const size_t row0 = (size_t)blockIdx.x * MTILE;

    // b2s + b1s live outside the staging regions — load once
    ((uint4*)(smem + OFF_B2S))[tid]       = ((const uint4*)b2)[tid];
    ((uint4*)(smem + OFF_B2S))[tid + 256] = ((const uint4*)b2)[tid + 256];
    if (tid < 32) ((float*)(smem + OFF_B1))[tid] = b1[tid];

    // ---- cp.async chunk issuer: A (x/h, 128x64 f32) + W1 (32x64 f32) ----
    auto issue_chunk = [&](int ck) {
        uint32_t ab = sb + ((ck & 1) ? OFF_A1 : OFF_A0);
        uint32_t wb = sb + ((ck & 1) ? OFF_W1B : OFF_W0);
        const float* src = ((ck < 8) ? x : h) + row0 * 512 + (size_t)(ck & 7) * 64;
        #pragma unroll
        for (int j = 0; j < 8; j++) {
            int i = tid + j * THREADS;            // 2048 16B segments
            int r = i >> 4, s = i & 15;
            CP16(ab + (uint32_t)(r * (ASTRIDE * 4) + s * 16),
                 (const char*)(src + (size_t)r * 512) + s * 16);
        }
        const float* wsrc = g_W1r + (size_t)(ck) * 64;
        #pragma unroll
        for (int j = 0; j < 2; j++) {
            int i = tid + j * THREADS;            // 512 16B segments
            int n = i >> 4, s = i & 15;
            CP16(wb + (uint32_t)(n * (ASTRIDE * 4) + s * 16),
                 (const char*)(wsrc + (size_t)n * 1024) + s * 16);
        }
        CP_COMMIT();
    };

    // ================= phase 1: GEMM1 via mma.sync tf32 =================
    float d[4][4];
    #pragma unroll
    for (int nt = 0; nt < 4; nt++)
        #pragma unroll
        for (int j = 0; j < 4; j++) d[nt][j] = 0.0f;

    issue_chunk(0);

    // fragment address components
    const int fr = lid >> 2, fk = lid & 3;
    const uint32_t aoff = (uint32_t)(((wid * 16 + fr) * ASTRIDE + fk) * 4);
    const uint32_t boff = (uint32_t)((fr * ASTRIDE + fk) * 4);   // + nt*8*ASTRIDE*4

    #pragma unroll 1
    for (int ck = 0; ck < NCHUNK; ck++) {
        if (ck + 1 < NCHUNK) { issue_chunk(ck + 1); CP_WAIT1(); }
        else                 { CP_WAIT0(); }
        __syncthreads();

        const uint32_t ab = sb + ((ck & 1) ? OFF_A1 : OFF_A0);
        const uint32_t wb = sb + ((ck & 1) ? OFF_W1B : OFF_W0);
        const uint32_t abase = ab + aoff;
        const uint32_t bbase = wb + boff;

        #pragma unroll
        for (int ks = 0; ks < 8; ks++) {
            const uint32_t ka = abase + ks * 32;
            uint32_t a0 = lds32(ka);
            uint32_t a1 = lds32(ka + 8 * ASTRIDE * 4);
            uint32_t a2 = lds32(ka + 16);
            uint32_t a3 = lds32(ka + 8 * ASTRIDE * 4 + 16);
            #pragma unroll
            for (int nt = 0; nt < 4; nt++) {
                const uint32_t kb = bbase + (uint32_t)(nt * 8 * ASTRIDE * 4) + ks * 32;
                uint32_t b0 = lds32(kb);
                uint32_t b1v = lds32(kb + 16);
                mma_tf32(d[nt], a0, a1, a2, a3, b0, b1v);
            }
        }
        __syncthreads();   // staging consumed; next issue may overwrite
    }

    // ---- z epilogue: bias + tanh -> f32 smem Z[row][ZSTRIDE]; overlay W2h ----
    {
        const float* b1s = (const float*)(smem + OFF_B1);
        float* zsm = (float*)(smem + OFF_Z);
        int rb = wid * 16 + (lid >> 2);
        int cb = (lid & 3) * 2;
        #pragma unroll
        for (int nt = 0; nt < 4; nt++) {
            int c0 = nt * 8 + cb;
            float bA = b1s[c0], bB = b1s[c0 + 1];
            float2 zlo = make_float2(tanh_acc(d[nt][0] + bA), tanh_acc(d[nt][1] + bB));
            float2 zhi = make_float2(tanh_acc(d[nt][2] + bA), tanh_acc(d[nt][3] + bB));
            *(float2*)(zsm + rb * ZSTRIDE + c0)       = zlo;
            *(float2*)(zsm + (rb + 8) * ZSTRIDE + c0) = zhi;
        }
        // W2h fp16 overlay (32 KB)
        uint4* dw = (uint4*)(smem + OFF_W2H);
        const uint4* swv = (const uint4*)g_W2h;
        #pragma unroll
        for (int j = 0; j < 8; j++) dw[tid + j * THREADS] = swv[tid + j * THREADS];
    }
    __syncthreads();

    // ================= phase 2: GEMM2 + gating, 4 rows per W2 pass =================
    const __half* W2h = (const __half*)(smem + OFF_W2H);
    const float* b2s = (const float*)(smem + OFF_B2S);
    const float* zf  = (const float*)(smem + OFF_Z);

    #pragma unroll 1
    for (int rb = 0; rb < 4; rb++) {
        const int r0 = wid * 16 + rb * 4;
        const size_t grow = row0 + r0;
        const float* zr = zf + r0 * ZSTRIDE;

        #pragma unroll 1
        for (int pass = 0; pass < 4; pass++) {
            const int hh = pass * 128 + lid * 4;

            float4 cv[4];
            #pragma unroll
            for (int i = 0; i < 4; i++)
                cv[i] = *(const float4*)(c + (grow + i) * (size_t)HID_SZ + hh);

            float preA[4][4], preB[4][4];
            gate_pre(W2h, b2s, zr, 0, hh, preA);   // i
            gate_pre(W2h, b2s, zr, 3, hh, preB);   // g
            float ig[4][4];
            #pragma unroll
            for (int i = 0; i < 4; i++)
                #pragma unroll
                for (int j = 0; j < 4; j++)
                    ig[i][j] = sigm_fast(preA[i][j]) * sigm_fast(preB[i][j]);
            gate_pre(W2h, b2s, zr, 1, hh, preA);   // f
            gate_pre(W2h, b2s, zr, 2, hh, preB);   // o

            #pragma unroll
            for (int i = 0; i < 4; i++) {
                float ca[4] = {cv[i].x, cv[i].y, cv[i].z, cv[i].w};
                float hn[4], cn[4];
                #pragma unroll
                for (int j = 0; j < 4; j++) {
                    float fg = sigm_fast(preA[i][j]);
                    float og = sigm_fast(preB[i][j]);
                    float cj = fmaf(fg, ca[j], ig[i][j]);
                    cn[j] = cj;
                    hn[j] = og * tanh_fast(cj);
                }
                float* hrow = out + (grow + i) * (size_t)HID_SZ;
                float* crw  = out + (size_t)B_SZ * HID_SZ + (grow + i) * (size_t)HID_SZ;
                *(float4*)(hrow + hh) = make_float4(hn[0], hn[1], hn[2], hn[3]);
                *(float4*)(crw  + hh) = make_float4(cn[0], cn[1], cn[2], cn[3]);
            }
        }
    }
}

extern "C" void kernel_launch(void* const* d_in, const int* in_sizes, int n_in,
                              void* d_out, int out_size) {
    const float* x  = (const float*)d_in[0];
    const float* h  = (const float*)d_in[1];
    const float* c  = (const float*)d_in[2];
    const float* W1 = (const float*)d_in[3];
    const float* b1 = (const float*)d_in[4];
    const float* W2 = (const float*)d_in[5];
    const float* b2 = (const float*)d_in[6];
    float* out = (float*)d_out;

    prep_kernel<<<192, 256>>>(W1, W2);   // 49152 threads: 32768 W1 + 16384 W2

    cudaFuncSetAttribute(lstm_kernel, cudaFuncAttributeMaxDynamicSharedMemorySize, SMEM_TOTAL);
    lstm_kernel<<<NBLK, THREADS, SMEM_TOTAL>>>(x, h, c, b1, b2, out);
}

// round 12
// speedup vs baseline: 2.8717x; 1.3010x over previous
#include <cuda_runtime.h>
#include <cstdint>

#define B_SZ    65536
#define HID_SZ  512
#define THREADS 256
#define NBLK    512        // 512 CTAs x 128 rows
#define MTILE   128
#define NCHUNK  16         // K = 1024 in chunks of 64
#define ASTRIDE 68         // f32 per A row (64 + 4 pad)
#define ZSTRIDE 36         // f32 per z row (36 mod 32 = 4 -> conflict-free A-frag LDS)
#define W2STRIDE 520       // f32 per W2 row (520 mod 32 = 8 -> conflict-free B-frag LDS)

typedef unsigned long long u64;

// ---------------- smem layout (bytes) ----------------
// phase1: A0 @0 (34816), A1 @34816 (->69632), W0 @69632 (8704), W1b @78336 (->87040)
// b2s @87040 (8192), b1 @95232 (128)
// phase2 overlay: W2s f32 [32][520] @0 (66560), Z @66560 (128*36*4=18432 ->84992)
#define OFF_A0    0
#define OFF_A1    34816
#define OFF_W0    69632
#define OFF_W1B   78336
#define OFF_B2S   87040
#define OFF_B1    95232
#define OFF_W2S   0
#define OFF_Z     66560
#define SMEM_TOTAL 95360

// ---------------- device globals (prep output) ----------------
__device__ __align__(16) float g_W1r[32 * 1024];   // W1 tf32-rounded, [gq][k]
__device__ __align__(16) float g_W2t[32 * 512];    // W2 transposed tf32-rounded, [gq][h]

// ---------------- helpers ----------------
__device__ __forceinline__ uint32_t smem_u32(const void* p) {
    uint32_t a;
    asm("{ .reg .u64 t; cvta.to.shared.u64 t, %1; cvt.u32.u64 %0, t; }" : "=r"(a) : "l"(p));
    return a;
}
__device__ __forceinline__ float tanh_acc(float xv) {
    float s = __fdividef(1.0f, 1.0f + __expf(-2.0f * xv));
    return 2.0f * s - 1.0f;
}
__device__ __forceinline__ float tanh_fast(float xv) {
    float y; asm("tanh.approx.f32 %0, %1;" : "=f"(y) : "f"(xv)); return y;
}
__device__ __forceinline__ float sigm_fast(float xv) {
    return fmaf(tanh_fast(0.5f * xv), 0.5f, 0.5f);
}
__device__ __forceinline__ uint32_t lds32(uint32_t a) {
    uint32_t v; asm volatile("ld.shared.b32 %0, [%1];" : "=r"(v) : "r"(a)); return v;
}
__device__ __forceinline__ float tf32r(float v) {
    float r; asm("cvt.rna.tf32.f32 %0, %1;" : "=f"(r) : "f"(v)); return r;
}
#define CP16(dst, src) \
    asm volatile("cp.async.ca.shared.global [%0], [%1], 16;" :: "r"(dst), "l"(src))
#define CP_COMMIT()  asm volatile("cp.async.commit_group;" ::: "memory")
#define CP_WAIT1()   asm volatile("cp.async.wait_group 1;" ::: "memory")
#define CP_WAIT0()   asm volatile("cp.async.wait_group 0;" ::: "memory")

__device__ __forceinline__ void mma_tf32(float* d, uint32_t a0, uint32_t a1,
                                         uint32_t a2, uint32_t a3,
                                         uint32_t b0, uint32_t b1) {
    asm volatile(
        "mma.sync.aligned.m16n8k8.row.col.f32.tf32.tf32.f32 "
        "{%0,%1,%2,%3}, {%4,%5,%6,%7}, {%8,%9}, {%0,%1,%2,%3};"
        : "+f"(d[0]), "+f"(d[1]), "+f"(d[2]), "+f"(d[3])
        : "r"(a0), "r"(a1), "r"(a2), "r"(a3), "r"(b0), "r"(b1));
}

// ---------------- prep: round W1/W2 to tf32; transpose W2 ----------------
__global__ void prep_kernel(const float* __restrict__ W1, const float* __restrict__ W2) {
    int t = blockIdx.x * blockDim.x + threadIdx.x;
    if (t < 32 * 1024) {
        g_W1r[t] = tf32r(W1[t]);                           // [gq][k] flat
    } else {
        int t2 = t - 32 * 1024;
        if (t2 < 32 * 512) {
            // dst [g][q][h] flat = [gq][h]; src W2[g][h][q]
            int g = t2 >> 12, rem = t2 & 4095, q = rem >> 9, hh = rem & 511;
            g_W2t[t2] = tf32r(W2[g * 4096 + hh * 8 + q]);
        }
    }
}

// ---------------- main fused kernel ----------------
__global__ __launch_bounds__(THREADS, 2)
void lstm_kernel(const float* __restrict__ x, const float* __restrict__ h,
                 const float* __restrict__ c, const float* __restrict__ b1,
                 const float* __restrict__ b2, float* __restrict__ out) {
    extern __shared__ __align__(16) char smem[];
    const uint32_t sb = smem_u32(smem);
    const int tid = threadIdx.x;
    const int wid = tid >> 5, lid = tid & 31;
    const size_t row0 = (size_t)blockIdx.x * MTILE;

    // b2s + b1s live outside all staging regions — load once
    ((uint4*)(smem + OFF_B2S))[tid]       = ((const uint4*)b2)[tid];
    ((uint4*)(smem + OFF_B2S))[tid + 256] = ((const uint4*)b2)[tid + 256];
    if (tid < 32) ((float*)(smem + OFF_B1))[tid] = b1[tid];

    // ---- cp.async chunk issuer: A (x/h, 128x64 f32) + W1 (32x64 f32) ----
    auto issue_chunk = [&](int ck) {
        uint32_t ab = sb + ((ck & 1) ? OFF_A1 : OFF_A0);
        uint32_t wb = sb + ((ck & 1) ? OFF_W1B : OFF_W0);
        const float* src = ((ck < 8) ? x : h) + row0 * 512 + (size_t)(ck & 7) * 64;
        #pragma unroll
        for (int j = 0; j < 8; j++) {
            int i = tid + j * THREADS;
            int r = i >> 4, s = i & 15;
            CP16(ab + (uint32_t)(r * (ASTRIDE * 4) + s * 16),
                 (const char*)(src + (size_t)r * 512) + s * 16);
        }
        const float* wsrc = g_W1r + (size_t)(ck) * 64;
        #pragma unroll
        for (int j = 0; j < 2; j++) {
            int i = tid + j * THREADS;
            int n = i >> 4, s = i & 15;
            CP16(wb + (uint32_t)(n * (ASTRIDE * 4) + s * 16),
                 (const char*)(wsrc + (size_t)n * 1024) + s * 16);
        }
        CP_COMMIT();
    };

    // ================= phase 1: GEMM1 via mma.sync tf32 =================
    float d[4][4];
    #pragma unroll
    for (int nt = 0; nt < 4; nt++)
        #pragma unroll
        for (int j = 0; j < 4; j++) d[nt][j] = 0.0f;

    issue_chunk(0);

    const int fr = lid >> 2, fk = lid & 3;
    const uint32_t aoff = (uint32_t)(((wid * 16 + fr) * ASTRIDE + fk) * 4);
    const uint32_t boff = (uint32_t)((fr * ASTRIDE + fk) * 4);

    #pragma unroll 1
    for (int ck = 0; ck < NCHUNK; ck++) {
        if (ck + 1 < NCHUNK) { issue_chunk(ck + 1); CP_WAIT1(); }
        else                 { CP_WAIT0(); }
        __syncthreads();

        const uint32_t ab = sb + ((ck & 1) ? OFF_A1 : OFF_A0);
        const uint32_t wb = sb + ((ck & 1) ? OFF_W1B : OFF_W0);
        const uint32_t abase = ab + aoff;
        const uint32_t bbase = wb + boff;

        #pragma unroll
        for (int ks = 0; ks < 8; ks++) {
            const uint32_t ka = abase + ks * 32;
            uint32_t a0 = lds32(ka);
            uint32_t a1 = lds32(ka + 8 * ASTRIDE * 4);
            uint32_t a2 = lds32(ka + 16);
            uint32_t a3 = lds32(ka + 8 * ASTRIDE * 4 + 16);
            #pragma unroll
            for (int nt = 0; nt < 4; nt++) {
                const uint32_t kb = bbase + (uint32_t)(nt * 8 * ASTRIDE * 4) + ks * 32;
                uint32_t b0 = lds32(kb);
                uint32_t b1v = lds32(kb + 16);
                mma_tf32(d[nt], a0, a1, a2, a3, b0, b1v);
            }
        }
        __syncthreads();
    }

    // ---- z epilogue: bias + tanh -> tf32-rounded f32 in Z; overlay W2s ----
    {
        const float* b1s = (const float*)(smem + OFF_B1);
        float* zsm = (float*)(smem + OFF_Z);
        int rb = wid * 16 + (lid >> 2);
        int cb = (lid & 3) * 2;
        #pragma unroll
        for (int nt = 0; nt < 4; nt++) {
            int c0 = nt * 8 + cb;
            float bA = b1s[c0], bB = b1s[c0 + 1];
            float2 zlo = make_float2(tf32r(tanh_acc(d[nt][0] + bA)),
                                     tf32r(tanh_acc(d[nt][1] + bB)));
            float2 zhi = make_float2(tf32r(tanh_acc(d[nt][2] + bA)),
                                     tf32r(tanh_acc(d[nt][3] + bB)));
            *(float2*)(zsm + rb * ZSTRIDE + c0)       = zlo;
            *(float2*)(zsm + (rb + 8) * ZSTRIDE + c0) = zhi;
        }
        // W2s overlay: [32 gq][520] f32; full 16384 floats = 4096 uint4
        // (R11 bug: only 1024 uint4 copied with wrong row stride)
        const uint4* swv = (const uint4*)g_W2t;
        #pragma unroll
        for (int j = 0; j < 16; j++) {
            int i = tid + j * THREADS;          // 4096 uint4
            int row = i >> 7, s = i & 127;      // 128 uint4 (512 f32) per source row
            *(uint4*)(smem + OFF_W2S + (uint32_t)((row * W2STRIDE + s * 4) * 4)) = swv[i];
        }
    }
    __syncthreads();

    // ================= phase 2: GEMM2 via mma.sync tf32 (K=8) + gating =================
    const float* b2s = (const float*)(smem + OFF_B2S);
    const int lr = lid >> 2;                    // frag row-in-group / B n index
    const int rbase = wid * 16;

    // A fragments (z): 4 gates x 4 regs, loaded ONCE, reused for all 64 h-subtiles
    uint32_t za[4][4];
    #pragma unroll
    for (int g = 0; g < 4; g++) {
        uint32_t base = sb + OFF_Z + (uint32_t)((((rbase + lr) * ZSTRIDE) + g * 8 + fk) * 4);
        za[g][0] = lds32(base);
        za[g][1] = lds32(base + 8 * ZSTRIDE * 4);
        za[g][2] = lds32(base + 16);
        za[g][3] = lds32(base + 8 * ZSTRIDE * 4 + 16);
    }

    const size_t r0g = row0 + rbase + lr;       // global row for frag row-low
    const float* c0p = c + r0g * HID_SZ;
    float* ho = out + r0g * HID_SZ;
    float* co = out + (size_t)B_SZ * HID_SZ + r0g * HID_SZ;

    #pragma unroll 2
    for (int s = 0; s < 64; s++) {
        const int hb = s * 8;
        const int hcol = hb + fk * 2;

        // c loads early (cover latency under MMA + gate math)
        float2 cva = *(const float2*)(c0p + hcol);
        float2 cvb = *(const float2*)(c0p + 8 * HID_SZ + hcol);

        // accumulators init = bias; one MMA per gate (K=8 complete)
        float dg[4][4];
        #pragma unroll
        for (int g = 0; g < 4; g++) {
            float2 bb = *(const float2*)(b2s + g * 512 + hcol);
            dg[g][0] = bb.x; dg[g][1] = bb.y; dg[g][2] = bb.x; dg[g][3] = bb.y;
            uint32_t wadr = sb + OFF_W2S + (uint32_t)((((g * 8 + fk) * W2STRIDE) + hb + lr) * 4);
            uint32_t b0 = lds32(wadr);                               // conflict-free
            uint32_t b1v = lds32(wadr + 4 * W2STRIDE * 4);
            mma_tf32(dg[g], za[g][0], za[g][1], za[g][2], za[g][3], b0, b1v);
        }

        // epilogue: lane owns (rowlow,col0),(rowlow,col1),(rowhigh,col0),(rowhigh,col1)
        float ca[4] = {cva.x, cva.y, cvb.x, cvb.y};
        float hn[4], cn[4];
        #pragma unroll
        for (int j = 0; j < 4; j++) {
            float ig = sigm_fast(dg[0][j]);
            float fg = sigm_fast(dg[1][j]);
            float og = sigm_fast(dg[2][j]);
            float gg = sigm_fast(dg[3][j]);
            float cj = fmaf(fg, ca[j], ig * gg);
            cn[j] = cj;
            hn[j] = og * tanh_fast(cj);
        }
        *(float2*)(ho + hcol)               = make_float2(hn[0], hn[1]);
        *(float2*)(ho + 8 * HID_SZ + hcol)  = make_float2(hn[2], hn[3]);
        *(float2*)(co + hcol)               = make_float2(cn[0], cn[1]);
        *(float2*)(co + 8 * HID_SZ + hcol)  = make_float2(cn[2], cn[3]);
    }
}

extern "C" void kernel_launch(void* const* d_in, const int* in_sizes, int n_in,
                              void* d_out, int out_size) {
    const float* x  = (const float*)d_in[0];
    const float* h  = (const float*)d_in[1];
    const float* c  = (const float*)d_in[2];
    const float* W1 = (const float*)d_in[3];
    const float* b1 = (const float*)d_in[4];
    const float* W2 = (const float*)d_in[5];
    const float* b2 = (const float*)d_in[6];
    float* out = (float*)d_out;

    prep_kernel<<<192, 256>>>(W1, W2);   // 49152 threads: 32768 W1 + 16384 W2

    cudaFuncSetAttribute(lstm_kernel, cudaFuncAttributeMaxDynamicSharedMemorySize, SMEM_TOTAL);
    lstm_kernel<<<NBLK, THREADS, SMEM_TOTAL>>>(x, h, c, b1, b2, out);
}